// round 4
// baseline (speedup 1.0000x reference)
#include <cuda_runtime.h>

#define PPC 2            // pixels per CTA
#define NTHREADS 256
#define VOTES_STRIDE 33  // 32 + 1 pad (gcd with 32 == 1)
#define LOGIT_STRIDE 17  // 16 + 1 pad

// Shared layout (floats):
//  votes : PPC * 256 * 33   (votes[p][m*33 + i], transposed, padded)
//  xs    : PPC * 256        (xs[p][i*8 + c])
//  logits: PPC * 32 * 17    (logits[p][i*17 + o], padded)
//  route : PPC * 32 * 16    (route[p][i*16 + o])
//  act   : PPC * 256        (act[p][o*16 + h])
#define VOTES_PP (256 * VOTES_STRIDE)      // 8448
#define LOGIT_PP (32 * LOGIT_STRIDE)       // 544
#define SMEM_FLOATS (PPC * (VOTES_PP + 256 + LOGIT_PP + 512 + 256))
#define SMEM_BYTES (SMEM_FLOATS * 4)

__global__ __launch_bounds__(NTHREADS)
void caps_route_kernel(const float* __restrict__ x,
                       const float* __restrict__ w,
                       const float* __restrict__ bias,
                       float* __restrict__ out) {
    extern __shared__ float sm[];
    float* votes  = sm;                                   // [PPC][8448]
    float* xs     = votes + PPC * VOTES_PP;               // [PPC][256]
    float* logits = xs + PPC * 256;                       // [PPC][544]
    float* route  = logits + PPC * LOGIT_PP;              // [PPC][512]
    float* act    = route + PPC * 512;                    // [PPC][256]

    const int tid  = threadIdx.x;
    const int pix0 = blockIdx.x * PPC;                    // pixel = b*256 + hw
    const int b    = pix0 >> 8;
    const int hw0  = pix0 & 255;

    // ---- Load x slice for this CTA's pixels: x[b, i, c, hw0 + p] ----
    {
        const int i = tid >> 3, c = tid & 7;
        const float* xp = x + (((b * 32 + i) * 8 + c) << 8) + hw0;
        #pragma unroll
        for (int p = 0; p < PPC; ++p)
            xs[p * 256 + tid] = xp[p];
    }
    // init logits (incl. padding) to zero
    for (int k = tid; k < PPC * LOGIT_PP; k += NTHREADS) logits[k] = 0.f;
    __syncthreads();

    // ---- votes[p][m][i] = sum_c xs[p][i][c] * w[i][c][m], thread owns m = tid ----
    {
        const int m = tid;
        #pragma unroll 4
        for (int i = 0; i < 32; ++i) {
            const float* wp = w + (i * 8) * 256 + m;
            float acc[PPC];
            #pragma unroll
            for (int p = 0; p < PPC; ++p) acc[p] = 0.f;
            #pragma unroll
            for (int c = 0; c < 8; ++c) {
                const float wv = wp[c * 256];
                #pragma unroll
                for (int p = 0; p < PPC; ++p)
                    acc[p] += xs[p * 256 + i * 8 + c] * wv;
            }
            #pragma unroll
            for (int p = 0; p < PPC; ++p)
                votes[p * VOTES_PP + m * VOTES_STRIDE + i] = acc[p];
        }
    }
    const float biasv = bias[tid];        // bias[o*16+h] == bias[m]
    const int o_idx = tid >> 4;
    float o_acc[PPC];
    __syncthreads();

    // ---- 3 routing iterations ----
    #pragma unroll 1
    for (int r = 0; r < 3; ++r) {
        // softmax over O for each (p, i): 64 threads, serial over 16
        if (tid < 32 * PPC) {
            const int p = tid >> 5, i = tid & 31;
            const float* lrow = logits + p * LOGIT_PP + i * LOGIT_STRIDE;
            float mx = lrow[0];
            #pragma unroll
            for (int o = 1; o < 16; ++o) mx = fmaxf(mx, lrow[o]);
            float e[16], s = 0.f;
            #pragma unroll
            for (int o = 0; o < 16; ++o) { e[o] = __expf(lrow[o] - mx); s += e[o]; }
            const float inv = __fdividef(1.f, s);
            float* rrow = route + p * 512 + i * 16;
            #pragma unroll
            for (int o = 0; o < 16; ++o) rrow[o] = e[o] * inv;
        }
        __syncthreads();

        // preact + squash: thread owns m = tid
        #pragma unroll
        for (int p = 0; p < PPC; ++p) {
            float acc = biasv;
            const float* vrow = votes + p * VOTES_PP + tid * VOTES_STRIDE;
            const float* rp   = route + p * 512 + o_idx;
            #pragma unroll 8
            for (int i = 0; i < 32; ++i)
                acc += rp[i * 16] * vrow[i];
            // squash: sum of squares over the 16 h-lanes (contiguous in warp)
            float ss = acc * acc;
            #pragma unroll
            for (int k = 8; k >= 1; k >>= 1)
                ss += __shfl_xor_sync(0xffffffffu, ss, k, 16);
            const float nrm = sqrtf(ss);
            const float a = acc * nrm / (1.f + ss);
            act[p * 256 + tid] = a;
            o_acc[p] = a;
        }
        __syncthreads();

        if (r < 2) {
            // distances[p][i][o] = sum_h votes[p][o*16+h][i] * act[p][o*16+h]
            // 1024 outputs, 256 threads, o fixed per warp -> conflict-free
            #pragma unroll
            for (int k = 0; k < 2 * PPC; ++k) {
                const int idx  = tid + k * NTHREADS;     // 0..1023
                const int p    = idx >> 9;
                const int lidx = idx & 511;
                const int o    = lidx >> 5;
                const int i    = lidx & 31;
                const float* ap = act + p * 256 + o * 16;
                const float* vp = votes + p * VOTES_PP + (o * 16) * VOTES_STRIDE + i;
                float d = 0.f;
                #pragma unroll
                for (int h = 0; h < 16; ++h)
                    d += vp[h * VOTES_STRIDE] * ap[h];
                logits[p * LOGIT_PP + i * LOGIT_STRIDE + o] += d;
            }
            __syncthreads();
        }
    }

    // ---- write out[b, o, h, hw] = out[(b*256 + m)*256 + hw] ----
    #pragma unroll
    for (int p = 0; p < PPC; ++p)
        out[((b << 8) + tid) * 256 + hw0 + p] = o_acc[p];
}

extern "C" void kernel_launch(void* const* d_in, const int* in_sizes, int n_in,
                              void* d_out, int out_size) {
    const float* x    = (const float*)d_in[0];
    const float* w    = (const float*)d_in[1];
    const float* bias = (const float*)d_in[2];
    float* out        = (float*)d_out;

    static bool attr_set = false;
    if (!attr_set) {
        cudaFuncSetAttribute(caps_route_kernel,
                             cudaFuncAttributeMaxDynamicSharedMemorySize, SMEM_BYTES);
        attr_set = true;
    }

    const int nblocks = (8 * 256) / PPC;   // 2048 pixels / PPC
    caps_route_kernel<<<nblocks, NTHREADS, SMEM_BYTES>>>(x, w, bias, out);
}

// round 6
// speedup vs baseline: 1.3584x; 1.3584x over previous
#include <cuda_runtime.h>
#include <cuda_fp16.h>

#define NT 256
#define P 2                      // pixels per CTA

// smem byte offsets (all 16B-aligned)
//  vB    : half [P*32][258]   (votes, m-contiguous, pad-2)  33024 B
//  xs    : float[P][256]                                     2048 B
//  routeT: float[P][16][32]   (route transposed)             4096 B
//  logit : float[P][32][17]                                  4352 B
//  act   : half [P][256]      (as half2 [P][128])            1024 B
#define OFF_VB     0
#define OFF_XS     33024
#define OFF_ROUTE  35072
#define OFF_LOGIT  39168
#define OFF_ACT    43520
#define SMEM_BYTES 44544

__global__ __launch_bounds__(NT, 4)
void caps_route_kernel(const float* __restrict__ x,
                       const float* __restrict__ w,
                       const float* __restrict__ bias,
                       float* __restrict__ out) {
    extern __shared__ char smem[];
    __half* vB     = (__half*)(smem + OFF_VB);
    float*  xs     = (float*) (smem + OFF_XS);
    float*  routeT = (float*) (smem + OFF_ROUTE);
    float*  logit  = (float*) (smem + OFF_LOGIT);
    __half2* act2  = (__half2*)(smem + OFF_ACT);
    __half2* vB2   = (__half2*)(smem + OFF_VB);   // word index = row*129 + m/2

    const int tid  = threadIdx.x;
    const int pix0 = blockIdx.x * P;
    const int b    = pix0 >> 8;
    const int hw0  = pix0 & 255;

    // ---- x load: thread = (i,c); 2 adjacent pixels as float2 ----
    {
        const float2 v = *(const float2*)(x + ((((b << 8) + tid) << 8) + hw0));
        xs[tid]       = v.x;
        xs[256 + tid] = v.y;
    }
    // init logits to 0, routeT to 1/16 (iteration-0 softmax of zero logits)
    for (int k = tid; k < P * 544; k += NT) logit[k] = 0.f;
    for (int k = tid; k < P * 512; k += NT) routeT[k] = 0.0625f;
    __syncthreads();

    // ---- votes: thread owns m = tid; vB[(p*32+i)*258 + m] = fp16 vote ----
    {
        const int m = tid;
        #pragma unroll 2
        for (int i = 0; i < 32; ++i) {
            const float4 xa0 = *(const float4*)(xs + i * 8);
            const float4 xb0 = *(const float4*)(xs + i * 8 + 4);
            const float4 xa1 = *(const float4*)(xs + 256 + i * 8);
            const float4 xb1 = *(const float4*)(xs + 256 + i * 8 + 4);
            const float* wp  = w + (i << 11) + m;          // i*8*256
            const float w0 = wp[0],        w1 = wp[256];
            const float w2 = wp[2 * 256],  w3 = wp[3 * 256];
            const float w4 = wp[4 * 256],  w5 = wp[5 * 256];
            const float w6 = wp[6 * 256],  w7 = wp[7 * 256];
            float a0 = xa0.x * w0 + xa0.y * w1 + xa0.z * w2 + xa0.w * w3
                     + xb0.x * w4 + xb0.y * w5 + xb0.z * w6 + xb0.w * w7;
            float a1 = xa1.x * w0 + xa1.y * w1 + xa1.z * w2 + xa1.w * w3
                     + xb1.x * w4 + xb1.y * w5 + xb1.z * w6 + xb1.w * w7;
            vB[i * 258 + m]          = __float2half_rn(a0);
            vB[(32 + i) * 258 + m]   = __float2half_rn(a1);
        }
    }
    __syncthreads();

    // ---- routing: thread owns pixel pp and m-pair (2*tt, 2*tt+1) ----
    const int pp = tid >> 7;
    const int tt = tid & 127;
    const int oo = tt >> 3;                       // capsule index o
    const float2 bv = *(const float2*)(bias + (tt << 1));
    float a0f = 0.f, a1f = 0.f;

    #pragma unroll 1
    for (int r = 0; r < 3; ++r) {
        if (r > 0) {
            // softmax over O for each (p,i): 64 threads
            if (tid < 64) {
                const int p = tid >> 5, i = tid & 31;
                const float* lr = logit + p * 544 + i * 17;
                float mx = lr[0];
                #pragma unroll
                for (int o = 1; o < 16; ++o) mx = fmaxf(mx, lr[o]);
                float e[16], s = 0.f;
                #pragma unroll
                for (int o = 0; o < 16; ++o) { e[o] = __expf(lr[o] - mx); s += e[o]; }
                const float inv = __fdividef(1.f, s);
                float* rr = routeT + p * 512 + i;          // rr[o*32]
                #pragma unroll
                for (int o = 0; o < 16; ++o) rr[o * 32] = e[o] * inv;
            }
            __syncthreads();
        }

        // preact + squash
        float acc0 = bv.x, acc1 = bv.y;
        const __half2* vp = vB2 + pp * 32 * 129 + tt;
        const float*   rp = routeT + pp * 512 + oo * 32;
        #pragma unroll
        for (int ii = 0; ii < 8; ++ii) {
            const float4 rr = *(const float4*)(rp + ii * 4);
            const float2 v0 = __half22float2(vp[(ii * 4 + 0) * 129]);
            const float2 v1 = __half22float2(vp[(ii * 4 + 1) * 129]);
            const float2 v2 = __half22float2(vp[(ii * 4 + 2) * 129]);
            const float2 v3 = __half22float2(vp[(ii * 4 + 3) * 129]);
            acc0 += rr.x * v0.x + rr.y * v1.x + rr.z * v2.x + rr.w * v3.x;
            acc1 += rr.x * v0.y + rr.y * v1.y + rr.z * v2.y + rr.w * v3.y;
        }
        // squash: sum of squares over 16 h (8 lanes x 2 values)
        float ss = acc0 * acc0 + acc1 * acc1;
        ss += __shfl_xor_sync(0xffffffffu, ss, 4);
        ss += __shfl_xor_sync(0xffffffffu, ss, 2);
        ss += __shfl_xor_sync(0xffffffffu, ss, 1);
        const float nrm = sqrtf(ss);
        const float sc  = nrm / (1.f + ss);
        a0f = acc0 * sc;
        a1f = acc1 * sc;
        act2[pp * 128 + tt] = __floats2half2_rn(a0f, a1f);
        __syncthreads();

        if (r < 2) {
            // distances[p][i][o] = sum_h votes[p][o*16+h][i] * act[p][o*16+h]
            #pragma unroll
            for (int k = 0; k < 4; ++k) {
                const int idx = tid + (k << 8);            // 0..1023
                const int p   = idx >> 9;
                const int o   = (idx >> 5) & 15;
                const int i   = idx & 31;
                const __half2* vq = vB2 + (p * 32 + i) * 129 + (o << 3);
                const __half2* aq = act2 + p * 128 + (o << 3);
                float d = 0.f;
                #pragma unroll
                for (int j = 0; j < 8; ++j) {
                    const float2 vv = __half22float2(vq[j]);
                    const float2 aa = __half22float2(aq[j]);
                    d += vv.x * aa.x + vv.y * aa.y;
                }
                logit[p * 544 + i * 17 + o] += d;
            }
            __syncthreads();
        }
    }

    // ---- out[b, m, hw]: thread owns (pp, 2tt, 2tt+1), fp32 from registers ----
    const int mbase = (b << 8) + (tt << 1);
    out[(mbase << 8) + hw0 + pp]         = a0f;
    out[((mbase + 1) << 8) + hw0 + pp]   = a1f;
}

extern "C" void kernel_launch(void* const* d_in, const int* in_sizes, int n_in,
                              void* d_out, int out_size) {
    const float* x    = (const float*)d_in[0];
    const float* w    = (const float*)d_in[1];
    const float* bias = (const float*)d_in[2];
    float* out        = (float*)d_out;

    static bool attr_set = false;
    if (!attr_set) {
        cudaFuncSetAttribute(caps_route_kernel,
                             cudaFuncAttributeMaxDynamicSharedMemorySize, SMEM_BYTES);
        attr_set = true;
    }

    const int nblocks = (8 * 256) / P;     // 1024
    caps_route_kernel<<<nblocks, NT, SMEM_BYTES>>>(x, w, bias, out);
}

// round 7
// speedup vs baseline: 1.6021x; 1.1794x over previous
#include <cuda_runtime.h>
#include <cuda_fp16.h>

#define NT 256
#define P 2                      // pixels per CTA

// smem byte offsets (16B-aligned)
//  vB    : half [64][258]   rows = p*32+i, stride 129 half2 words   33024 B
//  xs    : float[P][256]                                             2048 B
//  routeT: float[P][16][32] (route transposed)                       4096 B
//  logit : float[P][32][17]                                          4352 B
//  act   : half2[P][128]                                             1024 B
#define OFF_VB     0
#define OFF_XS     33024
#define OFF_ROUTE  35072
#define OFF_LOGIT  39168
#define OFF_ACT    43520
#define SMEM_BYTES 44544

__global__ __launch_bounds__(NT, 4)
void caps_route_kernel(const float* __restrict__ x,
                       const float* __restrict__ w,
                       const float* __restrict__ bias,
                       float* __restrict__ out) {
    extern __shared__ char smem[];
    float*   xs     = (float*)  (smem + OFF_XS);
    float*   routeT = (float*)  (smem + OFF_ROUTE);
    float*   logit  = (float*)  (smem + OFF_LOGIT);
    __half2* act2   = (__half2*)(smem + OFF_ACT);
    __half2* vB2    = (__half2*)(smem + OFF_VB);   // word index = row*129 + m/2

    const int tid  = threadIdx.x;
    const int pix0 = blockIdx.x * P;
    const int b    = pix0 >> 8;
    const int hw0  = pix0 & 255;

    // ---- x load: thread = (i,c) row; 2 adjacent pixels as float2 ----
    {
        const float2 v = *(const float2*)(x + ((((b << 8) + tid) << 8) + hw0));
        xs[tid]       = v.x;
        xs[256 + tid] = v.y;
    }
    for (int k = tid; k < P * 544; k += NT) logit[k] = 0.f;
    for (int k = tid; k < P * 512; k += NT) routeT[k] = 0.0625f;  // softmax of 0-logits
    __syncthreads();

    // ---- votes: thread = (i-group, m-quad). Each warp touches only 8 i's. ----
    {
        const int iq = tid >> 6;            // 0..3 -> i = iq*8 .. iq*8+7
        const int mq = (tid & 63) << 2;     // m quad base (0,4,...,252)
        #pragma unroll
        for (int ii = 0; ii < 8; ++ii) {
            const int i = (iq << 3) + ii;
            const float4 xa0 = *(const float4*)(xs + i * 8);
            const float4 xb0 = *(const float4*)(xs + i * 8 + 4);
            const float4 xa1 = *(const float4*)(xs + 256 + i * 8);
            const float4 xb1 = *(const float4*)(xs + 256 + i * 8 + 4);
            const float* wp = w + (i << 11) + mq;          // (i*8 + c)*256 + mq
            float4 a0 = make_float4(0.f, 0.f, 0.f, 0.f);
            float4 a1 = make_float4(0.f, 0.f, 0.f, 0.f);
            #pragma unroll
            for (int c = 0; c < 8; ++c) {
                const float4 wv = *(const float4*)(wp + (c << 8));
                const float x0 = (&xa0.x)[c & 3] * 0.f +   // (selector below)
                                 ((c < 4) ? (&xa0.x)[c] : (&xb0.x)[c - 4]);
                const float x1 = ((c < 4) ? (&xa1.x)[c] : (&xb1.x)[c - 4]);
                a0.x += x0 * wv.x; a0.y += x0 * wv.y; a0.z += x0 * wv.z; a0.w += x0 * wv.w;
                a1.x += x1 * wv.x; a1.y += x1 * wv.y; a1.z += x1 * wv.z; a1.w += x1 * wv.w;
            }
            __half2* d0 = vB2 + i * 129 + (mq >> 1);
            d0[0] = __floats2half2_rn(a0.x, a0.y);
            d0[1] = __floats2half2_rn(a0.z, a0.w);
            __half2* d1 = vB2 + (32 + i) * 129 + (mq >> 1);
            d1[0] = __floats2half2_rn(a1.x, a1.y);
            d1[1] = __floats2half2_rn(a1.z, a1.w);
        }
    }
    __syncthreads();

    // ---- routing: thread owns pixel pp, m-pair (2tt, 2tt+1) ----
    const int pp = tid >> 7;
    const int tt = tid & 127;
    const int oo = tt >> 3;
    const float2 bv = *(const float2*)(bias + (tt << 1));

    // load this thread's vote column ONCE into registers (reused 3x)
    __half2 v2[32];
    {
        const __half2* vcol = vB2 + pp * 32 * 129 + tt;
        #pragma unroll
        for (int i = 0; i < 32; ++i) v2[i] = vcol[i * 129];
    }

    float a0f = 0.f, a1f = 0.f;

    #pragma unroll 1
    for (int r = 0; r < 3; ++r) {
        if (r > 0) {
            if (tid < 64) {
                const int p = tid >> 5, i = tid & 31;
                const float* lr = logit + p * 544 + i * 17;
                float mx = lr[0];
                #pragma unroll
                for (int o = 1; o < 16; ++o) mx = fmaxf(mx, lr[o]);
                float e[16], s = 0.f;
                #pragma unroll
                for (int o = 0; o < 16; ++o) { e[o] = __expf(lr[o] - mx); s += e[o]; }
                const float inv = __fdividef(1.f, s);
                float* rr = routeT + p * 512 + i;          // rr[o*32]
                #pragma unroll
                for (int o = 0; o < 16; ++o) rr[o * 32] = e[o] * inv;
            }
            __syncthreads();
        }

        // preact from register votes + route broadcasts
        float acc0 = bv.x, acc1 = bv.y;
        const float* rp = routeT + pp * 512 + oo * 32;
        #pragma unroll
        for (int ii = 0; ii < 8; ++ii) {
            const float4 rr = *(const float4*)(rp + ii * 4);
            const float2 v0 = __half22float2(v2[ii * 4 + 0]);
            const float2 v1 = __half22float2(v2[ii * 4 + 1]);
            const float2 v2_ = __half22float2(v2[ii * 4 + 2]);
            const float2 v3 = __half22float2(v2[ii * 4 + 3]);
            acc0 += rr.x * v0.x + rr.y * v1.x + rr.z * v2_.x + rr.w * v3.x;
            acc1 += rr.x * v0.y + rr.y * v1.y + rr.z * v2_.y + rr.w * v3.y;
        }
        // squash over 16 h (8 lanes x 2)
        float ss = acc0 * acc0 + acc1 * acc1;
        ss += __shfl_xor_sync(0xffffffffu, ss, 4);
        ss += __shfl_xor_sync(0xffffffffu, ss, 2);
        ss += __shfl_xor_sync(0xffffffffu, ss, 1);
        const float sc = sqrtf(ss) / (1.f + ss);
        a0f = acc0 * sc;
        a1f = acc1 * sc;
        act2[pp * 128 + tt] = __floats2half2_rn(a0f, a1f);
        __syncthreads();

        if (r < 2) {
            // distances[p][i][o] = sum_h votes[p][o*16+h][i] * act[p][o*16+h]
            #pragma unroll
            for (int k = 0; k < 4; ++k) {
                const int idx = tid + (k << 8);            // 0..1023
                const int p   = idx >> 9;
                const int o   = (idx >> 5) & 15;
                const int i   = idx & 31;
                const __half2* vq = vB2 + (p * 32 + i) * 129 + (o << 3);
                const __half2* aq = act2 + p * 128 + (o << 3);
                float d = 0.f;
                #pragma unroll
                for (int j = 0; j < 8; ++j) {
                    const float2 vv = __half22float2(vq[j]);
                    const float2 aa = __half22float2(aq[j]);
                    d += vv.x * aa.x + vv.y * aa.y;
                }
                logit[p * 544 + i * 17 + o] += d;
            }
            __syncthreads();
        }
    }

    // ---- out[b, m, hw] from registers ----
    const int mbase = (b << 8) + (tt << 1);
    out[(mbase << 8) + hw0 + pp]       = a0f;
    out[((mbase + 1) << 8) + hw0 + pp] = a1f;
}

extern "C" void kernel_launch(void* const* d_in, const int* in_sizes, int n_in,
                              void* d_out, int out_size) {
    const float* x    = (const float*)d_in[0];
    const float* w    = (const float*)d_in[1];
    const float* bias = (const float*)d_in[2];
    float* out        = (float*)d_out;

    static bool attr_set = false;
    if (!attr_set) {
        cudaFuncSetAttribute(caps_route_kernel,
                             cudaFuncAttributeMaxDynamicSharedMemorySize, SMEM_BYTES);
        attr_set = true;
    }

    const int nblocks = (8 * 256) / P;     // 1024
    caps_route_kernel<<<nblocks, NT, SMEM_BYTES>>>(x, w, bias, out);
}